// round 9
// baseline (speedup 1.0000x reference)
#include <cuda_runtime.h>
#include <cuda_fp16.h>
#include <math.h>
#include <stdint.h>

// Problem shape (fixed by the dataset)
#define NE_MAX 100000
#define NR_MAX 1000
#define E_MAX  500000

// ---------------- scratch (device globals: no allocation allowed) -------------
// NOTE: zero-initialized at module load; kernels restore zeros each run so
// every graph replay sees identical initial state (no k_init launch needed).
__device__ float  g_HE[NE_MAX * 128];    // Ent@W_h (fp32, exact path)
__device__ __half g_TEh[NE_MAX * 128];   // Ent@W_t (fp16 message table)
__device__ __half g_REh[NR_MAX * 128];   // Rel@W_r (fp16 message table)
__device__ float  g_sh[NE_MAX];
__device__ float  g_st[NE_MAX];
__device__ float  g_sr[NR_MAX];
__device__ int    g_deg[NE_MAX];         // zeroed by k_scan_add after use
__device__ int    g_off[NE_MAX + 1];
__device__ int    g_cur[NE_MAX];
__device__ unsigned int g_smax[NE_MAX];  // zeroed by k_fused after use
__device__ int    g_bsum[128];
__device__ uint2  g_es[E_MAX];           // CSR-ordered (score bits, rr<<17|tt)

// ---------------- helpers ------------------------------------------------------
__device__ __forceinline__ uint32_t f2tf32(float x) {
    uint32_t r;
    asm("cvt.rna.tf32.f32 %0, %1;" : "=r"(r) : "f"(x));
    return r;
}

__device__ __forceinline__ unsigned int fkey(float f) {
    unsigned int u = __float_as_uint(f);
    return (u & 0x80000000u) ? ~u : (u | 0x80000000u);
}
__device__ __forceinline__ float funkey(unsigned int k) {
    return __uint_as_float((k & 0x80000000u) ? (k ^ 0x80000000u) : ~k);
}

__device__ __forceinline__ void mma_tf32(float4& c,
                                         uint32_t a0, uint32_t a1, uint32_t a2, uint32_t a3,
                                         uint32_t b0, uint32_t b1) {
    asm volatile(
        "mma.sync.aligned.m16n8k8.row.col.f32.tf32.tf32.f32 "
        "{%0,%1,%2,%3}, {%4,%5,%6,%7}, {%8,%9}, {%0,%1,%2,%3};\n"
        : "+f"(c.x), "+f"(c.y), "+f"(c.z), "+f"(c.w)
        : "r"(a0), "r"(a1), "r"(a2), "r"(a3), "r"(b0), "r"(b1));
}

// ---------------- K1: tensor-core GEMM + fused attention dot -------------------
// 64-row tiles, 2 warps of 32 rows each: every B fragment (LDS.128) is reused
// for two 16-row groups, halving B-side shared traffic per output element.
//  As2[row][p], p = ks*8 + tig*2 + khalf  (k = ks*8 + tig + 4*khalf) -> LDS.64
//  Ws2[k][gid*16 + j]  (col = j*8 + gid)                            -> LDS.128
#define A_PAD2 136   // mod 32 == 8
#define W_PAD2 132   // mod 32 == 4
#define GEMM_SMEM_BYTES ((64 * A_PAD2 + 128 * W_PAD2 + 128) * 4)

__global__ __launch_bounds__(64) void k_gemm_tc(
    const float* __restrict__ A, int n_rows,
    const float* __restrict__ W, int woff0, int woff1,
    float* __restrict__ Cf,        // fp32 out (yy==0 when half_yy0==0)
    __half* __restrict__ Ch,       // fp16 out
    int half_yy0,
    float* __restrict__ dot0, float* __restrict__ dot1,
    const float* __restrict__ a_vec)
{
    extern __shared__ uint32_t smem[];
    uint32_t* As2 = smem;                        // [64][A_PAD2]
    uint32_t* Ws2 = As2 + 64 * A_PAD2;           // [128][W_PAD2]
    float*    a_s = (float*)(Ws2 + 128 * W_PAD2);

    const int t    = threadIdx.x;    // 0..63
    const int warp = t >> 5;         // 0..1
    const int lane = t & 31;
    const int gid  = lane >> 2;
    const int tig  = lane & 3;
    const int row0 = blockIdx.x * 64;
    const int yy   = blockIdx.y;
    const int woff = yy == 0 ? woff0 : woff1;
    const bool use_half = (yy == 1) || half_yy0;
    float* dotp = yy == 0 ? dot0 : dot1;

    // stage A tile (64 x 128) into permuted layout: 2048 float4 / 64 threads
#pragma unroll
    for (int i = 0; i < 32; i++) {
        int idx = t + i * 64;
        int r   = idx >> 5;
        int c4  = (idx & 31) * 4;
        float4 v = make_float4(0.f, 0.f, 0.f, 0.f);
        int gr = row0 + r;
        if (gr < n_rows) v = *(const float4*)&A[gr * 128 + c4];
        uint32_t* dst = &As2[r * A_PAD2];
        int k = c4;
        int p = ((k >> 3) << 3) + ((k & 3) << 1) + ((k >> 2) & 1);
        dst[p]     = f2tf32(v.x);
        dst[p + 2] = f2tf32(v.y);
        dst[p + 4] = f2tf32(v.z);
        dst[p + 6] = f2tf32(v.w);
    }
    // stage W tile (128 x 128): 4096 float4 / 64 threads
#pragma unroll
    for (int i = 0; i < 64; i++) {
        int idx = t + i * 64;
        int r   = idx >> 5;
        int c4  = (idx & 31) * 4;
        float4 v = *(const float4*)&W[(woff + r) * 128 + c4];
        uint32_t* dst = &Ws2[r * W_PAD2];
        int p0 = ((c4 & 7) << 4) + (c4 >> 3);
        int p1 = (((c4 + 1) & 7) << 4) + ((c4 + 1) >> 3);
        int p2 = (((c4 + 2) & 7) << 4) + ((c4 + 2) >> 3);
        int p3 = (((c4 + 3) & 7) << 4) + ((c4 + 3) >> 3);
        dst[p0] = f2tf32(v.x); dst[p1] = f2tf32(v.y);
        dst[p2] = f2tf32(v.z); dst[p3] = f2tf32(v.w);
    }
    a_s[t] = a_vec[t];
    a_s[t + 64] = a_vec[t + 64];
    __syncthreads();

    float4 caccA[16], caccB[16];
#pragma unroll
    for (int j = 0; j < 16; j++) {
        caccA[j] = make_float4(0.f, 0.f, 0.f, 0.f);
        caccB[j] = make_float4(0.f, 0.f, 0.f, 0.f);
    }

    const int raA = 32 * warp + gid;           // rows raA, raA+8
    const uint32_t* Ar1A = &As2[raA * A_PAD2 + tig * 2];
    const uint32_t* Ar2A = &As2[(raA + 8) * A_PAD2 + tig * 2];
    const uint32_t* Ar1B = &As2[(raA + 16) * A_PAD2 + tig * 2];
    const uint32_t* Ar2B = &As2[(raA + 24) * A_PAD2 + tig * 2];
#pragma unroll
    for (int ks = 0; ks < 16; ks++) {
        uint2 avA1 = *(const uint2*)&Ar1A[ks * 8];
        uint2 avA2 = *(const uint2*)&Ar2A[ks * 8];
        uint2 avB1 = *(const uint2*)&Ar1B[ks * 8];
        uint2 avB2 = *(const uint2*)&Ar2B[ks * 8];
        const uint32_t* Br0 = &Ws2[(ks * 8 + tig) * W_PAD2 + gid * 16];
        const uint32_t* Br1 = &Ws2[(ks * 8 + tig + 4) * W_PAD2 + gid * 16];
#pragma unroll
        for (int c = 0; c < 4; c++) {
            uint4 b0 = *(const uint4*)&Br0[c * 4];
            uint4 b1 = *(const uint4*)&Br1[c * 4];
            mma_tf32(caccA[4 * c + 0], avA1.x, avA2.x, avA1.y, avA2.y, b0.x, b1.x);
            mma_tf32(caccA[4 * c + 1], avA1.x, avA2.x, avA1.y, avA2.y, b0.y, b1.y);
            mma_tf32(caccA[4 * c + 2], avA1.x, avA2.x, avA1.y, avA2.y, b0.z, b1.z);
            mma_tf32(caccA[4 * c + 3], avA1.x, avA2.x, avA1.y, avA2.y, b0.w, b1.w);
            mma_tf32(caccB[4 * c + 0], avB1.x, avB2.x, avB1.y, avB2.y, b0.x, b1.x);
            mma_tf32(caccB[4 * c + 1], avB1.x, avB2.x, avB1.y, avB2.y, b0.y, b1.y);
            mma_tf32(caccB[4 * c + 2], avB1.x, avB2.x, avB1.y, avB2.y, b0.z, b1.z);
            mma_tf32(caccB[4 * c + 3], avB1.x, avB2.x, avB1.y, avB2.y, b0.w, b1.w);
        }
    }

    // epilogue: store C (fp32 or fp16) and fused dot with a, for both groups
    const int rg1 = row0 + 32 * warp + gid;      // group A rows
    const int rg2 = rg1 + 8;
    const int rg3 = rg1 + 16;                    // group B rows
    const int rg4 = rg1 + 24;
    const bool v1 = rg1 < n_rows, v2 = rg2 < n_rows;
    const bool v3 = rg3 < n_rows, v4 = rg4 < n_rows;
    float p1 = 0.f, p2 = 0.f, p3 = 0.f, p4 = 0.f;
#pragma unroll
    for (int j = 0; j < 16; j++) {
        int cl = j * 8 + 2 * tig;
        float ax = a_s[cl], ay = a_s[cl + 1];
        p1 += caccA[j].x * ax + caccA[j].y * ay;
        p2 += caccA[j].z * ax + caccA[j].w * ay;
        p3 += caccB[j].x * ax + caccB[j].y * ay;
        p4 += caccB[j].z * ax + caccB[j].w * ay;
        if (use_half) {
            if (v1) *(__half2*)&Ch[rg1 * 128 + cl] = __floats2half2_rn(caccA[j].x, caccA[j].y);
            if (v2) *(__half2*)&Ch[rg2 * 128 + cl] = __floats2half2_rn(caccA[j].z, caccA[j].w);
            if (v3) *(__half2*)&Ch[rg3 * 128 + cl] = __floats2half2_rn(caccB[j].x, caccB[j].y);
            if (v4) *(__half2*)&Ch[rg4 * 128 + cl] = __floats2half2_rn(caccB[j].z, caccB[j].w);
        } else {
            if (v1) *(float2*)&Cf[rg1 * 128 + cl] = make_float2(caccA[j].x, caccA[j].y);
            if (v2) *(float2*)&Cf[rg2 * 128 + cl] = make_float2(caccA[j].z, caccA[j].w);
            if (v3) *(float2*)&Cf[rg3 * 128 + cl] = make_float2(caccB[j].x, caccB[j].y);
            if (v4) *(float2*)&Cf[rg4 * 128 + cl] = make_float2(caccB[j].z, caccB[j].w);
        }
    }
    p1 += __shfl_xor_sync(0xFFFFFFFFu, p1, 1);
    p1 += __shfl_xor_sync(0xFFFFFFFFu, p1, 2);
    p2 += __shfl_xor_sync(0xFFFFFFFFu, p2, 1);
    p2 += __shfl_xor_sync(0xFFFFFFFFu, p2, 2);
    p3 += __shfl_xor_sync(0xFFFFFFFFu, p3, 1);
    p3 += __shfl_xor_sync(0xFFFFFFFFu, p3, 2);
    p4 += __shfl_xor_sync(0xFFFFFFFFu, p4, 1);
    p4 += __shfl_xor_sync(0xFFFFFFFFu, p4, 2);
    if (tig == 0) {
        if (v1) dotp[rg1] = p1;
        if (v2) dotp[rg2] = p2;
        if (v3) dotp[rg3] = p3;
        if (v4) dotp[rg4] = p4;
    }
}

// ---------------- K3: histogram of destination degrees ------------------------
__global__ void k_hist(const int* __restrict__ h_index, int e) {
    int i = blockIdx.x * blockDim.x + threadIdx.x;
    if (i < e) atomicAdd(&g_deg[h_index[i]], 1);
}

// ---------------- K4a: per-block exclusive scan + block sums -------------------
__global__ __launch_bounds__(1024) void k_scan_blk(int n) {
    __shared__ int warp_tot[32];
    const int t = threadIdx.x;
    const int lane = t & 31;
    const int wid = t >> 5;
    int i = blockIdx.x * 1024 + t;
    int v = (i < n) ? g_deg[i] : 0;
    int s = v;
#pragma unroll
    for (int d = 1; d < 32; d <<= 1) {
        int x = __shfl_up_sync(0xFFFFFFFFu, s, d);
        if (lane >= d) s += x;
    }
    if (lane == 31) warp_tot[wid] = s;
    __syncthreads();
    if (wid == 0) {
        int wv = warp_tot[lane];
        int ws = wv;
#pragma unroll
        for (int d = 1; d < 32; d <<= 1) {
            int x = __shfl_up_sync(0xFFFFFFFFu, ws, d);
            if (lane >= d) ws += x;
        }
        warp_tot[lane] = ws - wv;
    }
    __syncthreads();
    int excl = warp_tot[wid] + s - v;
    if (i < n) g_off[i] = excl;            // block-local exclusive
    if (t == 1023) g_bsum[blockIdx.x] = excl + v;
}

// ---------------- K4b: top-level scan of block sums (nb <= 128) ---------------
__global__ __launch_bounds__(128) void k_scan_top(int nb, int etot, int n) {
    __shared__ int wt[4];
    const int t = threadIdx.x;
    const int lane = t & 31;
    const int wid = t >> 5;
    int v = (t < nb) ? g_bsum[t] : 0;
    int s = v;
#pragma unroll
    for (int d = 1; d < 32; d <<= 1) {
        int x = __shfl_up_sync(0xFFFFFFFFu, s, d);
        if (lane >= d) s += x;
    }
    if (lane == 31) wt[wid] = s;
    __syncthreads();
    int off = 0;
#pragma unroll
    for (int k = 0; k < 4; k++) if (k < wid) off += wt[k];
    g_bsum[t] = off + s - v;               // exclusive
    if (t == 0) g_off[n] = etot;
}

// ---------------- K4c: add block offsets, init cursors, reset deg -------------
__global__ __launch_bounds__(1024) void k_scan_add(int n) {
    int i = blockIdx.x * 1024 + threadIdx.x;
    if (i < n) {
        int o = g_off[i] + g_bsum[blockIdx.x];
        g_off[i] = o;
        g_cur[i] = o;
        g_deg[i] = 0;                      // restore for next replay
    }
}

// ---------------- K5: scatter edge records + segment max ----------------------
__global__ void k_scatter(const int* __restrict__ h_index, const int* __restrict__ r_index,
                          const int* __restrict__ t_index, const float* __restrict__ a_b,
                          int e) {
    int i = blockIdx.x * blockDim.x + threadIdx.x;
    if (i < e) {
        int hh = h_index[i];
        int rr = r_index[i];
        int tt = t_index[i];
        float s = (g_sh[hh] + a_b[0]) + (g_sr[rr] + g_st[tt]);
        s = (s >= 0.f) ? s : 0.2f * s;     // inner leaky
        s = (s >= 0.f) ? s : 0.2f * s;     // outer leaky
        int p = atomicAdd(&g_cur[hh], 1);
        g_es[p] = make_uint2(__float_as_uint(s), ((unsigned)rr << 17) | (unsigned)tt);
        atomicMax(&g_smax[hh], fkey(s));
    }
}

// ---------------- K6: fused segment softmax + reduce + bias + relu ------------
// One warp per destination; single pass (max precomputed by scatter).
__global__ void k_fused(const float* __restrict__ bias,
                        float* __restrict__ out, int ne)
{
    int w = (blockIdx.x * blockDim.x + threadIdx.x) >> 5;
    int lane = threadIdx.x & 31;
    if (w >= ne) return;
    int o0 = g_off[w];
    int deg = g_off[w + 1] - o0;
    float4 b4 = *(const float4*)&bias[lane * 4];
    float4 res;
    if (deg == 0) {
        res.x = fmaxf(b4.x, 0.f); res.y = fmaxf(b4.y, 0.f);
        res.z = fmaxf(b4.z, 0.f); res.w = fmaxf(b4.w, 0.f);
    } else {
        float m = funkey(g_smax[w]);
        float denom = 0.f;
        float4 acc = make_float4(0.f, 0.f, 0.f, 0.f);
        for (int base = 0; base < deg; base += 32) {
            int n = min(32, deg - base);
            float wgt = 0.f;
            unsigned pk = 0;
            if (lane < n) {
                uint2 er = g_es[o0 + base + lane];
                wgt = __expf(__uint_as_float(er.x) - m);
                pk = er.y;
            }
            denom += wgt;
#pragma unroll 4
            for (int j = 0; j < n; j++) {
                float wg = __shfl_sync(0xFFFFFFFFu, wgt, j);
                unsigned pj = __shfl_sync(0xFFFFFFFFu, pk, j);
                int rr = pj >> 17;
                int tt = pj & 0x1FFFF;
                __half2 fr0 = *(const __half2*)&g_REh[rr * 128 + lane * 4];
                __half2 fr1 = *(const __half2*)&g_REh[rr * 128 + lane * 4 + 2];
                __half2 ft0 = *(const __half2*)&g_TEh[tt * 128 + lane * 4];
                __half2 ft1 = *(const __half2*)&g_TEh[tt * 128 + lane * 4 + 2];
                float2 a0 = __half22float2(fr0), a1 = __half22float2(fr1);
                float2 c0 = __half22float2(ft0), c1 = __half22float2(ft1);
                acc.x += wg * (a0.x + c0.x);
                acc.y += wg * (a0.y + c0.y);
                acc.z += wg * (a1.x + c1.x);
                acc.w += wg * (a1.y + c1.y);
            }
        }
#pragma unroll
        for (int d = 16; d; d >>= 1) denom += __shfl_xor_sync(0xFFFFFFFFu, denom, d);
        float inv = 1.f / denom;
        float4 he = *(const float4*)&g_HE[w * 128 + lane * 4];
        res.x = fmaxf(he.x + acc.x * inv + b4.x, 0.f);
        res.y = fmaxf(he.y + acc.y * inv + b4.y, 0.f);
        res.z = fmaxf(he.z + acc.z * inv + b4.z, 0.f);
        res.w = fmaxf(he.w + acc.w * inv + b4.w, 0.f);
    }
    if (lane == 0) g_smax[w] = 0u;          // restore for next replay
    *(float4*)&out[w * 128 + lane * 4] = res;
}

// ---------------- host ---------------------------------------------------------
extern "C" void kernel_launch(void* const* d_in, const int* in_sizes, int n_in,
                              void* d_out, int out_size)
{
    const int*   h_index = (const int*)d_in[0];
    const int*   r_index = (const int*)d_in[1];
    const int*   t_index = (const int*)d_in[2];
    const float* ent     = (const float*)d_in[3];
    const float* rel     = (const float*)d_in[4];
    const float* W       = (const float*)d_in[5];
    const float* a       = (const float*)d_in[6];
    const float* a_b     = (const float*)d_in[7];
    const float* bias    = (const float*)d_in[8];
    float* out = (float*)d_out;

    const int E  = in_sizes[0];
    const int NE = in_sizes[3] / 128;
    const int NR = in_sizes[4] / 128;

    float*  p_HE;  cudaGetSymbolAddress((void**)&p_HE,  g_HE);
    __half* p_TEh; cudaGetSymbolAddress((void**)&p_TEh, g_TEh);
    __half* p_REh; cudaGetSymbolAddress((void**)&p_REh, g_REh);
    float*  p_sh;  cudaGetSymbolAddress((void**)&p_sh,  g_sh);
    float*  p_st;  cudaGetSymbolAddress((void**)&p_st,  g_st);
    float*  p_sr;  cudaGetSymbolAddress((void**)&p_sr,  g_sr);

    cudaFuncSetAttribute(k_gemm_tc, cudaFuncAttributeMaxDynamicSharedMemorySize,
                         GEMM_SMEM_BYTES);

    const int nb = (NE + 1023) / 1024;     // scan blocks (<=128 for NE<=131072)

    // HE (fp32) / TE (fp16) = Ent @ [W_h | W_t], fused sh/st dots
    {
        dim3 grid((NE + 63) / 64, 2);
        k_gemm_tc<<<grid, 64, GEMM_SMEM_BYTES>>>(ent, NE, W, 0, 256,
                                                 p_HE, p_TEh, 0, p_sh, p_st, a);
    }
    // RE (fp16) = Rel @ W_r, fused sr dot
    {
        dim3 grid((NR + 63) / 64, 1);
        k_gemm_tc<<<grid, 64, GEMM_SMEM_BYTES>>>(rel, NR, W, 128, 128,
                                                 (float*)0, p_REh, 1, p_sr, p_sr, a);
    }
    // CSR build by destination (h_index)
    k_hist<<<(E + 1023) / 1024, 1024>>>(h_index, E);
    k_scan_blk<<<nb, 1024>>>(NE);
    k_scan_top<<<1, 128>>>(nb, E, NE);
    k_scan_add<<<nb, 1024>>>(NE);
    // scatter packed edge records + per-segment max
    k_scatter<<<(E + 1023) / 1024, 1024>>>(h_index, r_index, t_index, a_b, E);
    // fused softmax + message reduce + bias + relu (single pass)
    k_fused<<<(NE * 32 + 255) / 256, 256>>>(bias, out, NE);
}